// round 17
// baseline (speedup 1.0000x reference)
#include <cuda_runtime.h>
#include <cuda_bf16.h>
#include <cstdint>
#include <math.h>

#define TT 256
#define BB 32
#define HH 256
#define KK 48
#define GATES 1024          // 4*H
#define ROWS_TB (TT*BB)     // 8192

// ---------------- device scratch (no allocations allowed) ----------------
__device__ float g_x0[ROWS_TB * 256];        // embedded input (t,b,e)
__device__ float g_gxf[ROWS_TB * GATES];     // x@Wih^T + b, fwd
__device__ float g_gxb[ROWS_TB * GATES];     // x@Wih^T + b, bwd
__device__ float g_h1[ROWS_TB * 512];        // layer-0 output (hf|hb)
__device__ float g_h2[ROWS_TB * 512];        // layer-1 output
__device__ float g_emit[ROWS_TB * KK];       // emissions (t,b,k)
__device__ float g_scr[BB];                  // per-batch (num-den)

// L2-exchange: h[par][dir][bg][b*256+u], flags [dir][bg][rank] (counters, +128/step)
__device__ float g_hx[2 * 2 * 8 * 1024];     // 128 KB
__device__ int   g_flag[2 * 8 * 8];          // 128 ints

// output layout: [emit (B,T,K) fp32 | loss | mask (B,T)]
#define EMIT_N   (BB*TT*KK)      // 393216
#define LOSS_OFF EMIT_N
#define MASK_OFF (EMIT_N + 1)

// ---------------- helpers ----------------
__device__ __forceinline__ float sigf(float x) { return 1.0f / (1.0f + __expf(-x)); }
__device__ __forceinline__ float tanh_fast(float x) {
    return 2.0f / (1.0f + __expf(-2.0f * x)) - 1.0f;
}

__device__ __forceinline__ uint32_t smem_u32(const void* p) {
    uint32_t a;
    asm("{ .reg .u64 t; cvta.to.shared.u64 t, %1; cvt.u32.u64 %0, t; }" : "=r"(a) : "l"(p));
    return a;
}
// pack (lo half = a, hi half = b) into bf16x2
__device__ __forceinline__ uint32_t pk2(float a, float b) {
    uint32_t r;
    asm("cvt.rn.bf16x2.f32 %0, %1, %2;" : "=r"(r) : "f"(b), "f"(a));
    return r;
}
// packed fp32x2 helpers (sm_100+ dual-FMA path)
__device__ __forceinline__ unsigned long long pk64(float lo, float hi) {
    unsigned long long v;
    asm("mov.b64 %0, {%1, %2};" : "=l"(v) : "f"(lo), "f"(hi));
    return v;
}
__device__ __forceinline__ void fma2(unsigned long long& acc, unsigned long long a,
                                     unsigned long long b) {
    asm("fma.rn.f32x2 %0, %1, %2, %0;" : "+l"(acc) : "l"(a), "l"(b));
}
__device__ __forceinline__ float hsum2(unsigned long long v) {
    float lo, hi;
    asm("mov.b64 {%0, %1}, %2;" : "=f"(lo), "=f"(hi) : "l"(v));
    return lo + hi;
}
__device__ __forceinline__ void ldm_x4(uint32_t* r, uint32_t addr) {
    asm volatile("ldmatrix.sync.aligned.m8n8.x4.shared.b16 {%0,%1,%2,%3}, [%4];"
                 : "=r"(r[0]), "=r"(r[1]), "=r"(r[2]), "=r"(r[3]) : "r"(addr));
}
__device__ __forceinline__ void ldm_x2(uint32_t* r, uint32_t addr) {
    asm volatile("ldmatrix.sync.aligned.m8n8.x2.shared.b16 {%0,%1}, [%2];"
                 : "=r"(r[0]), "=r"(r[1]) : "r"(addr));
}
__device__ __forceinline__ void mma16816(float* c, const uint32_t* a, const uint32_t* b) {
    asm volatile("mma.sync.aligned.m16n8k16.row.col.f32.bf16.bf16.f32 "
                 "{%0,%1,%2,%3}, {%4,%5,%6,%7}, {%8,%9}, {%0,%1,%2,%3};"
                 : "+f"(c[0]), "+f"(c[1]), "+f"(c[2]), "+f"(c[3])
                 : "r"(a[0]), "r"(a[1]), "r"(a[2]), "r"(a[3]), "r"(b[0]), "r"(b[1]));
}
__device__ __forceinline__ int ld_acq(const int* p) {
    int v;
    asm volatile("ld.acquire.gpu.global.s32 %0, [%1];" : "=r"(v) : "l"(p) : "memory");
    return v;
}
// per-producer release-increment on the step counter: orders this thread's
// prior global stores (the h publish) before the increment, no block fence.
__device__ __forceinline__ void red_add_release(int* p, int v) {
    asm volatile("red.release.gpu.global.add.s32 [%0], %1;" :: "l"(p), "r"(v) : "memory");
}

// ---------------- embedding gather ----------------
__global__ void embed_kernel(const int* __restrict__ sent,
                             const float* __restrict__ embed,
                             float* __restrict__ x0) {
    int bid = blockIdx.x;            // t*32 + b
    int t = bid >> 5, b = bid & 31;
    int tok = sent[b * TT + t];
    x0[(size_t)bid * 256 + threadIdx.x] = embed[(size_t)tok * 256 + threadIdx.x];
}

// ---------------- mma.sync bf16x3 GEMM: C[M,N] = A[M,K] * W[N,K]^T + bias ----------------
#define MG_AHI 0
#define MG_ALO 18432
#define MG_BHI 36864
#define MG_BLO 46080
#define MG_TOTAL 55296
#define APITCH 72

__global__ void __launch_bounds__(256)
mma_gemm(const float* __restrict__ A,
         const float* __restrict__ Wf, const float* __restrict__ Wb,
         const float* __restrict__ biasf, const float* __restrict__ biasb,
         float* __restrict__ Cf, float* __restrict__ Cb,
         int K, int Nout) {
    extern __shared__ char smc[];
    uint32_t sb = smem_u32(smc);
    int tid = threadIdx.x, wid = tid >> 5, l = tid & 31;
    int m0 = blockIdx.y * 128, n0 = blockIdx.x * 64;
    const float* W    = blockIdx.z ? Wb : Wf;
    const float* bias = blockIdx.z ? biasb : biasf;
    float*       C    = blockIdx.z ? Cb : Cf;

    int wm = wid & 3, wn = wid >> 2;
    int srow = tid >> 4;
    int scol = (tid & 15) << 2;

    float c[2][4][4];
#pragma unroll
    for (int mi = 0; mi < 2; mi++)
#pragma unroll
        for (int ni = 0; ni < 4; ni++)
#pragma unroll
            for (int j = 0; j < 4; j++) c[mi][ni][j] = 0.0f;

    int nch = K >> 6;
    for (int ch = 0; ch < nch; ch++) {
        int kc = ch << 6;
#pragma unroll
        for (int rr = 0; rr < 8; rr++) {
            int row = srow + rr * 16;
            float4 v = *(const float4*)&A[(size_t)(m0 + row) * K + kc + scol];
            float hx = __bfloat162float(__float2bfloat16(v.x));
            float hy = __bfloat162float(__float2bfloat16(v.y));
            float hz = __bfloat162float(__float2bfloat16(v.z));
            float hw = __bfloat162float(__float2bfloat16(v.w));
            uint32_t off = (uint32_t)(row * APITCH + scol) * 2;
            *(uint2*)(smc + MG_AHI + off) = make_uint2(pk2(hx, hy), pk2(hz, hw));
            *(uint2*)(smc + MG_ALO + off) =
                make_uint2(pk2(v.x - hx, v.y - hy), pk2(v.z - hz, v.w - hw));
        }
#pragma unroll
        for (int rr = 0; rr < 4; rr++) {
            int row = srow + rr * 16;
            int n = n0 + row;
            float4 v = make_float4(0.f, 0.f, 0.f, 0.f);
            if (n < Nout) v = *(const float4*)&W[(size_t)n * K + kc + scol];
            float hx = __bfloat162float(__float2bfloat16(v.x));
            float hy = __bfloat162float(__float2bfloat16(v.y));
            float hz = __bfloat162float(__float2bfloat16(v.z));
            float hw = __bfloat162float(__float2bfloat16(v.w));
            uint32_t off = (uint32_t)(row * APITCH + scol) * 2;
            *(uint2*)(smc + MG_BHI + off) = make_uint2(pk2(hx, hy), pk2(hz, hw));
            *(uint2*)(smc + MG_BLO + off) =
                make_uint2(pk2(v.x - hx, v.y - hy), pk2(v.z - hz, v.w - hw));
        }
        __syncthreads();

#pragma unroll
        for (int ks = 0; ks < 4; ks++) {
            uint32_t ah[2][4], al[2][4];
#pragma unroll
            for (int mi = 0; mi < 2; mi++) {
                uint32_t off =
                    (uint32_t)((wm * 32 + mi * 16 + (l & 15)) * APITCH +
                               ks * 16 + (l >> 4) * 8) * 2;
                ldm_x4(ah[mi], sb + MG_AHI + off);
                ldm_x4(al[mi], sb + MG_ALO + off);
            }
            uint32_t bh[4][2], bl[4][2];
#pragma unroll
            for (int ni = 0; ni < 4; ni++) {
                uint32_t off =
                    (uint32_t)((wn * 32 + ni * 8 + (l & 7)) * APITCH +
                               ks * 16 + ((l >> 3) & 1) * 8) * 2;
                ldm_x2(bh[ni], sb + MG_BHI + off);
                ldm_x2(bl[ni], sb + MG_BLO + off);
            }
#pragma unroll
            for (int mi = 0; mi < 2; mi++)
#pragma unroll
                for (int ni = 0; ni < 4; ni++) {
                    mma16816(c[mi][ni], ah[mi], bh[ni]);
                    mma16816(c[mi][ni], al[mi], bh[ni]);
                    mma16816(c[mi][ni], ah[mi], bl[ni]);
                }
        }
        __syncthreads();
    }

#pragma unroll
    for (int mi = 0; mi < 2; mi++) {
#pragma unroll
        for (int ni = 0; ni < 4; ni++) {
#pragma unroll
            for (int j = 0; j < 4; j++) {
                int row = m0 + wm * 32 + mi * 16 + (l >> 2) + (j >> 1) * 8;
                int col = n0 + wn * 32 + ni * 8 + (l & 3) * 2 + (j & 1);
                if (col < Nout)
                    C[(size_t)row * Nout + col] = c[mi][ni][j] + bias[col];
            }
        }
    }
}

// ---------------- reset for the L2-exchange state (run before each lstm launch) ----
__global__ void lstm_reset() {
    int idx = blockIdx.x * blockDim.x + threadIdx.x;
    if (idx < 2 * 2 * 8 * 1024) g_hx[idx] = 0.0f;
    if (idx < 2 * 8 * 8) g_flag[idx] = 0;
}

// ---------------- BiLSTM layer v12: per-warp pipelined poll+copy ----------------
// R16 structure (FFMA2 matvec, fused tail, red.release counters). Change:
// warp w polls ONLY rank w's counter and copies rank w's slice immediately,
// so early ranks' copies overlap late ranks' polls; one sync converges.
#define OFF_HBUF 0                                // 2048 floats (2 par x 1024)
#define OFF_RED  2048                             // 4*528 floats = 2112
#define OFF_CSM  (OFF_RED + 2112)                 // 128 floats
#define LSTM_SMEM_FLOATS (OFF_CSM + 128)          // 4288
#define LSTM_SMEM_BYTES  (LSTM_SMEM_FLOATS * 4)   // 17152

__global__ void __launch_bounds__(256, 1)
lstm_layer(const float* __restrict__ GxF, const float* __restrict__ GxB,
           const float* __restrict__ WhhF, const float* __restrict__ WhhB,
           const int* __restrict__ lengths, float* __restrict__ Hout) {
    extern __shared__ float sm[];
    float* hbuf = sm + OFF_HBUF;
    float* red  = sm + OFF_RED;
    float* csm  = sm + OFF_CSM;

    int tid = threadIdx.x;
    int l   = tid & 31;
    int wd  = tid >> 5;                      // warp id 0..7 (= rank it serves)
    int r   = blockIdx.x & 7;
    int cid = blockIdx.x >> 3;
    int dir = cid >> 3;
    int bg  = cid & 7;
    int batch0 = bg * 4;

    const float* Gx  = dir ? GxB : GxF;
    const float* Whh = dir ? WhhB : WhhF;

    float* hx_base  = g_hx;                       // [par][dir][bg][1024]
    int*   flg_base = g_flag + (dir * 8 + bg) * 8;

    // matvec thread mapping: gate pair + k-quarter
    int gp = tid & 63;
    int kq = tid >> 6;
    int g0 = gp << 1, g1 = g0 + 1;
    int grow0 = ((g0 >> 5) << 8) + (r << 5) + (g0 & 31);
    int grow1 = ((g1 >> 5) << 8) + (r << 5) + (g1 & 31);

    // W slice into b64 register pairs: 2 gates x 64 k (32 pairs each)
    unsigned long long w0p[32], w1p[32];
    {
        const float4* p0 = (const float4*)(Whh + (size_t)grow0 * 256 + kq * 64);
        const float4* p1 = (const float4*)(Whh + (size_t)grow1 * 256 + kq * 64);
#pragma unroll
        for (int i = 0; i < 16; i++) {
            float4 a = p0[i], b = p1[i];
            w0p[2 * i]     = pk64(a.x, a.y);
            w0p[2 * i + 1] = pk64(a.z, a.w);
            w1p[2 * i]     = pk64(b.x, b.y);
            w1p[2 * i + 1] = pk64(b.z, b.w);
        }
    }
    if (tid < 128) csm[tid] = 0.0f;
    __syncthreads();

    // per-warp copy mapping: warp wd copies rank wd's slice
    // (4 batches x 32 floats at b*256 + wd*32); lane l: batch l>>3, float4 l&7
    int cb = l >> 3;                         // batch 0..3
    int cf = l & 7;                          // float4 index within 32-float chunk
    uint32_t coff = (uint32_t)(cb * 256 + wd * 32 + cf * 4);

    int b2 = tid >> 5, uu = tid & 31;        // producer/tail mapping (tid<128)
    int mylen = 0;
    if (tid < 128) mylen = lengths[batch0 + b2];
    float hreg = 0.0f;

    for (int s = 0; s < TT; ++s) {
        int t = dir ? (TT - 1 - s) : s;
        int par = s & 1;

        // prefetch gate-x for this step before polling (tid<128: batch b2, unit uu)
        float gxi = 0.f, gxfv = 0.f, gxg = 0.f, gxo = 0.f;
        if (tid < 128) {
            const float* gpx = Gx + ((size_t)t * BB + batch0 + b2) * GATES + (r << 5) + uu;
            gxi = gpx[0]; gxfv = gpx[256]; gxg = gpx[512]; gxo = gpx[768];
        }

        // per-warp poll+copy: warp wd waits for rank wd, copies its slice.
        // Early ranks' copies overlap late ranks' polls.
        {
            if (s > 0) {
                int need = 128 * s;
                while (ld_acq(flg_base + wd) < need) { }
            }
            const float* src = hx_base + ((par * 2 + dir) * 8 + bg) * 1024 + coff;
            float4 v = __ldcg((const float4*)src);
            *(float4*)&hbuf[par * 1024 + coff] = v;
        }
        __syncthreads();

        // matvec (FFMA2): 2 gates x 4 batches x 64 k; W in b64 reg pairs,
        // h via SMEM broadcast reinterpreted as b64 pairs
        const float* hb = hbuf + par * 1024 + kq * 64;
        unsigned long long ac0[4] = {0ull, 0ull, 0ull, 0ull};
        unsigned long long ac1[4] = {0ull, 0ull, 0ull, 0ull};
#pragma unroll
        for (int i = 0; i < 16; i++) {
#pragma unroll
            for (int b = 0; b < 4; b++) {
                ulonglong2 hp = *(const ulonglong2*)(hb + b * 256 + i * 4);
                fma2(ac0[b], w0p[2 * i],     hp.x);
                fma2(ac0[b], w0p[2 * i + 1], hp.y);
                fma2(ac1[b], w1p[2 * i],     hp.x);
                fma2(ac1[b], w1p[2 * i + 1], hp.y);
            }
        }
        // partials batch-major: red[b*528 + kq*132 + g]
#pragma unroll
        for (int b = 0; b < 4; b++) {
            red[b * 528 + kq * 132 + g0] = hsum2(ac0[b]);
            red[b * 528 + kq * 132 + g1] = hsum2(ac1[b]);
        }
        __syncthreads();

        // fused assemble + gates + publish (tid<128: batch b2, unit uu)
        if (tid < 128) {
            const float* rb = red + b2 * 528;
            float iv = rb[0 * 132 + uu]       + rb[1 * 132 + uu]
                     + rb[2 * 132 + uu]       + rb[3 * 132 + uu]       + gxi;
            float fv = rb[0 * 132 + 32 + uu]  + rb[1 * 132 + 32 + uu]
                     + rb[2 * 132 + 32 + uu]  + rb[3 * 132 + 32 + uu]  + gxfv;
            float gv = rb[0 * 132 + 64 + uu]  + rb[1 * 132 + 64 + uu]
                     + rb[2 * 132 + 64 + uu]  + rb[3 * 132 + 64 + uu]  + gxg;
            float ov = rb[0 * 132 + 96 + uu]  + rb[1 * 132 + 96 + uu]
                     + rb[2 * 132 + 96 + uu]  + rb[3 * 132 + 96 + uu]  + gxo;
            float c  = csm[b2 * 32 + uu];
            float c2 = sigf(fv) * c + sigf(iv) * tanh_fast(gv);
            float h2 = sigf(ov) * tanh_fast(c2);
            bool m = (t < mylen);
            float hn = m ? h2 : hreg;
            float cn = m ? c2 : c;
            csm[b2 * 32 + uu] = cn;
            hreg = hn;

            if (s < TT - 1) {
                // publish own slice for step s+1, then release-increment the
                // flag counter (orders THIS thread's h store before the add)
                hx_base[(((par ^ 1) * 2 + dir) * 8 + bg) * 1024 +
                        (b2 << 8) + (r << 5) + uu] = hn;
                red_add_release(flg_base + r, 1);
            }
            // Hout (DRAM) AFTER signaling — off the critical path
            Hout[((size_t)t * BB + batch0 + b2) * 512 + dir * 256 + (r << 5) + uu] =
                m ? h2 : 0.0f;
        }
        // no trailing syncthreads: next iteration's post-copy sync covers
        // red/hbuf reuse (copy writes the opposite parity hbuf half)
    }
}

// ---------------- emit transpose + mask output ----------------
__global__ void finalize_kernel(const float* __restrict__ emitb,
                                const int* __restrict__ sent,
                                float* __restrict__ out, int out_size) {
    int bid = blockIdx.x;            // b*256 + t
    int b = bid >> 8, t = bid & 255;
    int k = threadIdx.x;
    if (k < KK) out[(size_t)bid * KK + k] = emitb[((size_t)t * BB + b) * KK + k];
    if (k == KK) {
        int idx = MASK_OFF + bid;
        if (idx < out_size) out[idx] = (sent[bid] != 0) ? 1.0f : 0.0f;
    }
}

// ---------------- CRF v2: 96 threads, 2 threads per tag, fast exp/log ----------------
__global__ void crf_kernel(const float* __restrict__ emitb,
                           const int* __restrict__ tags,
                           const int* __restrict__ lengths,
                           const float* __restrict__ start_t,
                           const float* __restrict__ end_t,
                           const float* __restrict__ trans,
                           float* __restrict__ scratch) {
    int b = blockIdx.x;
    int tid = threadIdx.x;           // 96
    __shared__ float trs[KK * KK];
    __shared__ float score[KK];
    __shared__ float rbuf[64];
    __shared__ float numsh;

    for (int i = tid; i < KK * KK; i += 96) trs[i] = trans[i];
    int len = lengths[b];
    __syncthreads();

    // numerator on threads 0..63 (deterministic fixed-tree reduction)
    if (tid < 64) {
        float part = 0.0f;
        for (int t = 1 + tid; t < len; t += 64) {
            int tg = tags[b * TT + t];
            int pg = tags[b * TT + t - 1];
            part += trs[pg * KK + tg] + emitb[((size_t)t * BB + b) * KK + tg];
        }
        rbuf[tid] = part;
    }
    __syncthreads();
    for (int s = 32; s > 0; s >>= 1) {
        if (tid < s) rbuf[tid] += rbuf[tid + s];
        __syncthreads();
    }
    if (tid == 0) {
        int t0 = tags[b * TT + 0];
        numsh = rbuf[0] + start_t[t0] + emitb[(size_t)b * KK + t0]
              + end_t[tags[b * TT + len - 1]];
    }

    // denominator: forward algorithm, 2 threads per k (j split 24/24)
    int k    = tid >> 1;             // 0..47
    int half = tid & 1;
    int jb   = half * 24;

    if (tid < KK) score[tid] = start_t[tid] + emitb[(size_t)b * KK + tid];
    __syncthreads();
    for (int t = 1; t < len; t++) {
        float m = -1e30f;
#pragma unroll 4
        for (int j = 0; j < 24; j++) {
            float v = score[jb + j] + trs[(jb + j) * KK + k];
            m = fmaxf(m, v);
        }
        float m2 = fmaxf(m, __shfl_xor_sync(0xffffffffu, m, 1));
        float ssum = 0.0f;
#pragma unroll 4
        for (int j = 0; j < 24; j++)
            ssum += __expf(score[jb + j] + trs[(jb + j) * KK + k] - m2);
        ssum += __shfl_xor_sync(0xffffffffu, ssum, 1);
        float nv = m2 + __logf(ssum) + emitb[((size_t)t * BB + b) * KK + k];
        __syncthreads();
        if (half == 0) score[k] = nv;
        __syncthreads();
    }
    if (tid == 0) {
        float m = -1e30f;
        for (int kk2 = 0; kk2 < KK; kk2++) m = fmaxf(m, score[kk2] + end_t[kk2]);
        float ssum = 0.0f;
        for (int kk2 = 0; kk2 < KK; kk2++) ssum += __expf(score[kk2] + end_t[kk2] - m);
        float den = m + __logf(ssum);
        scratch[b] = numsh - den;
    }
}

__global__ void loss_kernel(const float* __restrict__ scratch,
                            float* __restrict__ out, int out_size) {
    if (threadIdx.x == 0 && LOSS_OFF < out_size) {
        float s = 0.0f;
        for (int b = 0; b < BB; b++) s += scratch[b];
        out[LOSS_OFF] = s / (float)BB;
    }
}

// ---------------- launch ----------------
extern "C" void kernel_launch(void* const* d_in, const int* in_sizes, int n_in,
                              void* d_out, int out_size) {
    const int*   sentence = (const int*)d_in[0];
    const int*   lengths  = (const int*)d_in[1];
    const int*   tags     = (const int*)d_in[2];
    const float* embed    = (const float*)d_in[3];
    const float* Wih0f = (const float*)d_in[4];
    const float* Whh0f = (const float*)d_in[5];
    const float* b0f   = (const float*)d_in[6];
    const float* Wih0b = (const float*)d_in[7];
    const float* Whh0b = (const float*)d_in[8];
    const float* b0b   = (const float*)d_in[9];
    const float* Wih1f = (const float*)d_in[10];
    const float* Whh1f = (const float*)d_in[11];
    const float* b1f   = (const float*)d_in[12];
    const float* Wih1b = (const float*)d_in[13];
    const float* Whh1b = (const float*)d_in[14];
    const float* b1b   = (const float*)d_in[15];
    const float* Wout  = (const float*)d_in[16];
    const float* bout  = (const float*)d_in[17];
    const float* start_t = (const float*)d_in[18];
    const float* end_t   = (const float*)d_in[19];
    const float* trans   = (const float*)d_in[20];
    float* out = (float*)d_out;

    float *x0, *gxf, *gxb, *h1, *h2, *emitb, *scr;
    cudaGetSymbolAddress((void**)&x0, g_x0);
    cudaGetSymbolAddress((void**)&gxf, g_gxf);
    cudaGetSymbolAddress((void**)&gxb, g_gxb);
    cudaGetSymbolAddress((void**)&h1, g_h1);
    cudaGetSymbolAddress((void**)&h2, g_h2);
    cudaGetSymbolAddress((void**)&emitb, g_emit);
    cudaGetSymbolAddress((void**)&scr, g_scr);

    cudaFuncSetAttribute(lstm_layer, cudaFuncAttributeMaxDynamicSharedMemorySize,
                         LSTM_SMEM_BYTES);
    cudaFuncSetAttribute(mma_gemm, cudaFuncAttributeMaxDynamicSharedMemorySize,
                         MG_TOTAL);

    embed_kernel<<<ROWS_TB, 256>>>(sentence, embed, x0);

    // layer 0
    mma_gemm<<<dim3(16, 64, 2), 256, MG_TOTAL>>>(
        x0, Wih0f, Wih0b, b0f, b0b, gxf, gxb, 256, GATES);
    lstm_reset<<<128, 256>>>();
    lstm_layer<<<128, 256, LSTM_SMEM_BYTES>>>(gxf, gxb, Whh0f, Whh0b, lengths, h1);

    // layer 1
    mma_gemm<<<dim3(16, 64, 2), 256, MG_TOTAL>>>(
        h1, Wih1f, Wih1b, b1f, b1b, gxf, gxb, 512, GATES);
    lstm_reset<<<128, 256>>>();
    lstm_layer<<<128, 256, LSTM_SMEM_BYTES>>>(gxf, gxb, Whh1f, Whh1b, lengths, h2);

    // emissions
    mma_gemm<<<dim3(1, 64, 1), 256, MG_TOTAL>>>(
        h2, Wout, Wout, bout, bout, emitb, emitb, 512, KK);

    finalize_kernel<<<BB * TT, 64>>>(emitb, sentence, out, out_size);
    crf_kernel<<<BB, 96>>>(emitb, tags, lengths, start_t, end_t, trans, scr);
    loss_kernel<<<1, 32>>>(scr, out, out_size);
}